// round 1
// baseline (speedup 1.0000x reference)
#include <cuda_runtime.h>

#define NN 50000
#define NE 800000
#define NG 64
#define LRELU(x) ((x) > 0.f ? (x) : 0.2f*(x))

// ---------------- workspaces (static __device__, no allocation) ----------------
__device__ float d_c1[4];                                   // cl0, cl1, cr0, cr1
__device__ __align__(16) float d_m1[NN*2];                  // layer1 per-dst max (float bits)
__device__ __align__(16) float d_aux1[NN*4];                // {s0, num0, s1, num1}
__device__ __align__(16) float d_feat2[NN*32];
__device__ __align__(16) float d_res2p[NN*32];
__device__ float d_el2[NN];
__device__ float d_er2[NN];
__device__ float d_m2[NN];
__device__ float d_s2[NN];
__device__ __align__(16) float d_rst2[NN*32];
__device__ __align__(16) float d_h2[NN*32];

// ---------------- helpers ----------------
__device__ __forceinline__ void atomicMaxFloat(float* addr, float v) {
    int iv = __float_as_int(v);
    if (iv >= 0) atomicMax((int*)addr, iv);
    else         atomicMin((unsigned int*)addr, (unsigned int)iv);
}

__device__ __forceinline__ void redAdd4(float* addr, float a, float b, float c, float d) {
    asm volatile("red.global.add.v4.f32 [%0], {%1, %2, %3, %4};"
                 :: "l"(addr), "f"(a), "f"(b), "f"(c), "f"(d) : "memory");
}

// ---------------- init: fill maxes with -inf, sums with 0 ----------------
__global__ void k_init() {
    int i = blockIdx.x*blockDim.x + threadIdx.x;
    int stride = gridDim.x*blockDim.x;
    const int NINF = 0xFF800000;
    for (int j = i; j < NN*2;  j += stride) ((int*)d_m1)[j] = NINF;
    for (int j = i; j < NN*4;  j += stride) d_aux1[j] = 0.f;
    for (int j = i; j < NN;    j += stride) { ((int*)d_m2)[j] = NINF; d_s2[j] = 0.f; }
    for (int j = i; j < NN*32; j += stride) d_rst2[j] = 0.f;
}

// ---------------- layer1 attention constants: cl[h]=sum_d W1[h,d]*al1[h,d], cr likewise ----
__global__ void k_const(const float* __restrict__ W1, const float* __restrict__ al1,
                        const float* __restrict__ ar1) {
    __shared__ float sl[128], sr[128];
    int t = threadIdx.x;                 // 128 threads; hd = t, head = t>>6
    float w = W1[t];
    sl[t] = w * al1[t];
    sr[t] = w * ar1[t];
    __syncthreads();
    for (int off = 32; off > 0; off >>= 1) {
        if ((t & 63) < off) { sl[t] += sl[t+off]; sr[t] += sr[t+off]; }
        __syncthreads();
    }
    if ((t & 63) == 0) { d_c1[t>>6] = sl[t]; d_c1[2 + (t>>6)] = sr[t]; }
}

// ---------------- layer1 edge pass A: segment max ----------------
__global__ void k_e1max(const int* __restrict__ src, const int* __restrict__ dst,
                        const float* __restrict__ feat) {
    int e = blockIdx.x*blockDim.x + threadIdx.x;
    if (e >= NE) return;
    int s = src[e], d = dst[e];
    float fs = feat[s], fd = feat[d];
    float e0 = LRELU(d_c1[0]*fs + d_c1[2]*fd);
    float e1 = LRELU(d_c1[1]*fs + d_c1[3]*fd);
    atomicMaxFloat(&d_m1[d*2+0], e0);
    atomicMaxFloat(&d_m1[d*2+1], e1);
}

// ---------------- layer1 edge pass B: exp-sum + weighted feat sum (fused) ----------------
__global__ void k_e1sum(const int* __restrict__ src, const int* __restrict__ dst,
                        const float* __restrict__ feat) {
    int e = blockIdx.x*blockDim.x + threadIdx.x;
    if (e >= NE) return;
    int s = src[e], d = dst[e];
    float fs = feat[s], fd = feat[d];
    float e0 = LRELU(d_c1[0]*fs + d_c1[2]*fd);
    float e1 = LRELU(d_c1[1]*fs + d_c1[3]*fd);
    float a0 = __expf(e0 - d_m1[d*2+0]);
    float a1 = __expf(e1 - d_m1[d*2+1]);
    redAdd4(&d_aux1[d*4], a0, a0*fs, a1, a1*fs);
}

// ---------------- node kernel 1: h1 (registers) -> feat2, res2p, el2, er2 ----------------
__global__ void __launch_bounds__(256) k_node1(
    const float* __restrict__ feat, const float* __restrict__ W1,
    const float* __restrict__ res1, const float* __restrict__ b1,
    const float* __restrict__ g1g, const float* __restrict__ g1b,
    const float* __restrict__ g1m, const float* __restrict__ g1v,
    const float* __restrict__ W2, const float* __restrict__ res2,
    const float* __restrict__ al2, const float* __restrict__ ar2)
{
    __shared__ float sW2[128*32], sR2[128*32];
    __shared__ float sP[128], sQ[128], sR[128];
    __shared__ float sal2[32], sar2[32];
    int tid = threadIdx.x;
    for (int i = tid; i < 4096; i += 256) { sW2[i] = W2[i]; sR2[i] = res2[i]; }
    if (tid < 128) {
        float sc = g1g[tid] * rsqrtf(g1v[tid] + 1e-5f);
        sP[tid] = W1[tid]  * sc;
        sQ[tid] = res1[tid]* sc;
        sR[tid] = b1[tid]*sc + g1b[tid] - g1m[tid]*sc;
    }
    if (tid < 32) { sal2[tid] = al2[tid]; sar2[tid] = ar2[tid]; }
    __syncthreads();

    int lane = tid & 31;
    int wid  = blockIdx.x*8 + (tid >> 5);
    int nwarp = gridDim.x*8;

    for (int base = wid*4; base < NN; base += nwarp*4) {
        float h1v[4][4];
        float f2[4] = {0,0,0,0}, r2[4] = {0,0,0,0};
        #pragma unroll
        for (int m = 0; m < 4; m++) {
            int n = base + m;
            float f = feat[n];
            float4 aux = *(const float4*)&d_aux1[n*4];
            float t0 = aux.x > 0.f ? aux.y/aux.x : 0.f;
            float t1 = aux.z > 0.f ? aux.w/aux.z : 0.f;
            #pragma unroll
            for (int q = 0; q < 4; q++) {
                int hd = lane + 32*q;
                float th = (q < 2) ? t0 : t1;
                h1v[m][q] = fmaxf(fmaf(sP[hd], th, fmaf(sQ[hd], f, sR[hd])), 0.f);
            }
        }
        #pragma unroll
        for (int q = 0; q < 4; q++) {
            #pragma unroll 8
            for (int kk = 0; kk < 32; kk++) {
                int k = q*32 + kk;
                float w = sW2[k*32 + lane];
                float r = sR2[k*32 + lane];
                #pragma unroll
                for (int m = 0; m < 4; m++) {
                    float hk = __shfl_sync(0xffffffffu, h1v[m][q], kk);
                    f2[m] = fmaf(hk, w, f2[m]);
                    r2[m] = fmaf(hk, r, r2[m]);
                }
            }
        }
        #pragma unroll
        for (int m = 0; m < 4; m++) {
            int n = base + m;
            d_feat2[n*32 + lane] = f2[m];
            d_res2p[n*32 + lane] = r2[m];
            float vl = f2[m]*sal2[lane], vr = f2[m]*sar2[lane];
            #pragma unroll
            for (int o = 16; o > 0; o >>= 1) {
                vl += __shfl_xor_sync(0xffffffffu, vl, o);
                vr += __shfl_xor_sync(0xffffffffu, vr, o);
            }
            if (lane == 0) { d_el2[n] = vl; d_er2[n] = vr; }
        }
    }
}

// ---------------- layer2 edge pass A: segment max ----------------
__global__ void k_e2max(const int* __restrict__ src, const int* __restrict__ dst) {
    int e = blockIdx.x*blockDim.x + threadIdx.x;
    if (e >= NE) return;
    int s = src[e], d = dst[e];
    float ev = LRELU(d_el2[s] + d_er2[d]);
    atomicMaxFloat(&d_m2[d], ev);
}

// ---------------- layer2 edge pass B: exp-sum + 32-wide weighted scatter (8 lanes/edge) ----
__global__ void k_e2sum(const int* __restrict__ src, const int* __restrict__ dst) {
    long long t = (long long)blockIdx.x*blockDim.x + threadIdx.x;
    int e = (int)(t >> 3);
    int q = (int)(t & 7);
    if (e >= NE) return;
    int s = src[e], d = dst[e];
    float ev = LRELU(d_el2[s] + d_er2[d]);
    float a = __expf(ev - d_m2[d]);
    if (q == 0) atomicAdd(&d_s2[d], a);
    float4 v = *(const float4*)&d_feat2[s*32 + q*4];
    redAdd4(&d_rst2[d*32 + q*4], a*v.x, a*v.y, a*v.z, a*v.w);
}

// ---------------- node kernel 2: h2 + BN2 + ReLU, store h2, full decoder -> recon ----------
__global__ void __launch_bounds__(256) k_node2(
    const float* __restrict__ b2,
    const float* __restrict__ g2g, const float* __restrict__ g2b,
    const float* __restrict__ g2m, const float* __restrict__ g2v,
    const float* __restrict__ Wd1, const float* __restrict__ bd1,
    const float* __restrict__ gdg, const float* __restrict__ gdb,
    const float* __restrict__ gdm, const float* __restrict__ gdv,
    const float* __restrict__ Wd2, const float* __restrict__ bd2,
    float* __restrict__ out)
{
    __shared__ float sWd1[32*128];
    __shared__ float sSCD[128], sSHD[128], sWd2[128];
    __shared__ float sB2[32], sSC2[32], sSH2[32];
    int tid = threadIdx.x;
    for (int i = tid; i < 4096; i += 256) sWd1[i] = Wd1[i];
    if (tid < 128) {
        float sc = gdg[tid] * rsqrtf(gdv[tid] + 1e-5f);
        sSCD[tid] = sc;
        sSHD[tid] = fmaf(bd1[tid] - gdm[tid], sc, gdb[tid]);
        sWd2[tid] = Wd2[tid];
    }
    if (tid < 32) {
        float sc = g2g[tid] * rsqrtf(g2v[tid] + 1e-5f);
        sSC2[tid] = sc;
        sSH2[tid] = g2b[tid] - g2m[tid]*sc;
        sB2[tid]  = b2[tid];
    }
    __syncthreads();
    float bd2v = bd2[0];

    int lane = tid & 31;
    int wid  = blockIdx.x*8 + (tid >> 5);
    int nwarp = gridDim.x*8;

    for (int n = wid; n < NN; n += nwarp) {
        float s2v = d_s2[n];
        float rv  = d_rst2[n*32 + lane];
        float x = (s2v > 0.f ? rv/s2v : 0.f) + d_res2p[n*32 + lane] + sB2[lane];
        float h2v = fmaxf(fmaf(x, sSC2[lane], sSH2[lane]), 0.f);
        d_h2[n*32 + lane] = h2v;

        float y0 = 0.f, y1 = 0.f, y2 = 0.f, y3 = 0.f;
        #pragma unroll 8
        for (int k = 0; k < 32; k++) {
            float hk = __shfl_sync(0xffffffffu, h2v, k);
            y0 = fmaf(hk, sWd1[k*128 + lane     ], y0);
            y1 = fmaf(hk, sWd1[k*128 + lane + 32], y1);
            y2 = fmaf(hk, sWd1[k*128 + lane + 64], y2);
            y3 = fmaf(hk, sWd1[k*128 + lane + 96], y3);
        }
        float acc;
        acc  = fmaxf(fmaf(y0, sSCD[lane     ], sSHD[lane     ]), 0.f) * sWd2[lane     ];
        acc += fmaxf(fmaf(y1, sSCD[lane + 32], sSHD[lane + 32]), 0.f) * sWd2[lane + 32];
        acc += fmaxf(fmaf(y2, sSCD[lane + 64], sSHD[lane + 64]), 0.f) * sWd2[lane + 64];
        acc += fmaxf(fmaf(y3, sSCD[lane + 96], sSHD[lane + 96]), 0.f) * sWd2[lane + 96];
        #pragma unroll
        for (int o = 16; o > 0; o >>= 1) acc += __shfl_xor_sync(0xffffffffu, acc, o);
        if (lane == 0) out[2048 + n] = acc + bd2v;
    }
}

// ---------------- graph mean-pool (graph_ids sorted; binary-search bounds) ----------------
__global__ void k_pool(const int* __restrict__ gids, float* __restrict__ out) {
    int g = blockIdx.x;
    int a = 0, b = NN;
    while (a < b) { int mid = (a+b) >> 1; if (gids[mid] < g) a = mid+1; else b = mid; }
    int lo = a;
    a = lo; b = NN;
    while (a < b) { int mid = (a+b) >> 1; if (gids[mid] < g+1) a = mid+1; else b = mid; }
    int hi = a;

    __shared__ float sacc[256];
    int tid = threadIdx.x, lane = tid & 31, grp = tid >> 5;
    float acc = 0.f;
    for (int n = lo + grp; n < hi; n += 8) acc += d_h2[n*32 + lane];
    sacc[tid] = acc;
    __syncthreads();
    if (tid < 128) sacc[tid] += sacc[tid + 128];
    __syncthreads();
    if (tid < 64)  sacc[tid] += sacc[tid + 64];
    __syncthreads();
    if (tid < 32) {
        float v = sacc[tid] + sacc[tid + 32];
        float cnt = (float)(hi - lo);
        out[g*32 + tid] = v / fmaxf(cnt, 1.f);
    }
}

// ---------------- launch ----------------
extern "C" void kernel_launch(void* const* d_in, const int* in_sizes, int n_in,
                              void* d_out, int out_size) {
    const float* feat = (const float*)d_in[0];
    const float* W1   = (const float*)d_in[1];
    const float* al1  = (const float*)d_in[2];
    const float* ar1  = (const float*)d_in[3];
    const float* res1 = (const float*)d_in[4];
    const float* b1   = (const float*)d_in[5];
    const float* g1g  = (const float*)d_in[6];
    const float* g1b  = (const float*)d_in[7];
    const float* g1m  = (const float*)d_in[8];
    const float* g1v  = (const float*)d_in[9];
    const float* W2   = (const float*)d_in[10];
    const float* al2  = (const float*)d_in[11];
    const float* ar2  = (const float*)d_in[12];
    const float* res2 = (const float*)d_in[13];
    const float* b2   = (const float*)d_in[14];
    const float* g2g  = (const float*)d_in[15];
    const float* g2b  = (const float*)d_in[16];
    const float* g2m  = (const float*)d_in[17];
    const float* g2v  = (const float*)d_in[18];
    const float* Wd1  = (const float*)d_in[19];
    const float* bd1  = (const float*)d_in[20];
    const float* gdg  = (const float*)d_in[21];
    const float* gdb  = (const float*)d_in[22];
    const float* gdm  = (const float*)d_in[23];
    const float* gdv  = (const float*)d_in[24];
    const float* Wd2  = (const float*)d_in[25];
    const float* bd2  = (const float*)d_in[26];
    const int* src    = (const int*)d_in[27];
    const int* dst    = (const int*)d_in[28];
    const int* gids   = (const int*)d_in[29];
    float* out = (float*)d_out;

    k_init<<<1024, 256>>>();
    k_const<<<1, 128>>>(W1, al1, ar1);
    k_e1max<<<(NE + 255)/256, 256>>>(src, dst, feat);
    k_e1sum<<<(NE + 255)/256, 256>>>(src, dst, feat);
    k_node1<<<888, 256>>>(feat, W1, res1, b1, g1g, g1b, g1m, g1v, W2, res2, al2, ar2);
    k_e2max<<<(NE + 255)/256, 256>>>(src, dst);
    k_e2sum<<<(NE*8 + 255)/256, 256>>>(src, dst);
    k_node2<<<888, 256>>>(b2, g2g, g2b, g2m, g2v, Wd1, bd1, gdg, gdb, gdm, gdv, Wd2, bd2, out);
    k_pool<<<NG, 256>>>(gids, out);
}

// round 2
// speedup vs baseline: 1.2349x; 1.2349x over previous
#include <cuda_runtime.h>

#define NN 50000
#define NE 800000
#define NG 64
#define LRELU(x) ((x) > 0.f ? (x) : 0.2f*(x))

// ---------------- workspaces (static __device__, no allocation) ----------------
__device__ float d_c1[4];                                   // cl0, cl1, cr0, cr1
__device__ __align__(16) float d_aux1[NN*4];                // {s0, num0, s1, num1}
__device__ __align__(16) float d_feat2[NN*32];
__device__ __align__(16) float d_res2p[NN*32];
__device__ float d_el2[NN];
__device__ float d_er2[NN];
__device__ float d_s2[NN];
__device__ __align__(16) float d_rst2[NN*32];
__device__ __align__(16) float d_h2[NN*32];

// ---------------- helpers ----------------
__device__ __forceinline__ void redAdd4(float* addr, float a, float b, float c, float d) {
    asm volatile("red.global.add.v4.f32 [%0], {%1, %2, %3, %4};"
                 :: "l"(addr), "f"(a), "f"(b), "f"(c), "f"(d) : "memory");
}

// ---------------- init: zero accumulators + compute layer1 attention constants ----------
// consts: cl[h] = sum_d W1[h,d]*al1[h,d], cr[h] = sum_d W1[h,d]*ar1[h,d]  (done by block 0)
__global__ void k_init(const float* __restrict__ W1, const float* __restrict__ al1,
                       const float* __restrict__ ar1) {
    int i = blockIdx.x*blockDim.x + threadIdx.x;
    int stride = gridDim.x*blockDim.x;
    float4 z = make_float4(0.f, 0.f, 0.f, 0.f);
    for (int j = i; j < NN;    j += stride) ((float4*)d_aux1)[j] = z;
    for (int j = i; j < NN*8;  j += stride) ((float4*)d_rst2)[j] = z;
    for (int j = i; j < NN;    j += stride) d_s2[j] = 0.f;

    if (blockIdx.x == 0) {
        __shared__ float sl[128], sr[128];
        int t = threadIdx.x;
        if (t < 128) {
            float w = W1[t];
            sl[t] = w * al1[t];
            sr[t] = w * ar1[t];
        }
        __syncthreads();
        for (int off = 32; off > 0; off >>= 1) {
            if (t < 128 && (t & 63) < off) { sl[t] += sl[t+off]; sr[t] += sr[t+off]; }
            __syncthreads();
        }
        if (t < 128 && (t & 63) == 0) { d_c1[t>>6] = sl[t]; d_c1[2 + (t>>6)] = sr[t]; }
    }
}

// ---------------- layer1 edge pass (single, no max): exp-sum + weighted feat sum -------
__global__ void k_e1(const int* __restrict__ src, const int* __restrict__ dst,
                     const float* __restrict__ feat) {
    int e = blockIdx.x*blockDim.x + threadIdx.x;
    if (e >= NE) return;
    int s = src[e], d = dst[e];
    float fs = feat[s], fd = feat[d];
    float e0 = LRELU(d_c1[0]*fs + d_c1[2]*fd);
    float e1 = LRELU(d_c1[1]*fs + d_c1[3]*fd);
    float a0 = __expf(e0);
    float a1 = __expf(e1);
    redAdd4(&d_aux1[d*4], a0, a0*fs, a1, a1*fs);
}

// ---------------- node kernel 1: h1 (registers) -> feat2, res2p, el2, er2 ----------------
__global__ void __launch_bounds__(256) k_node1(
    const float* __restrict__ feat, const float* __restrict__ W1,
    const float* __restrict__ res1, const float* __restrict__ b1,
    const float* __restrict__ g1g, const float* __restrict__ g1b,
    const float* __restrict__ g1m, const float* __restrict__ g1v,
    const float* __restrict__ W2, const float* __restrict__ res2,
    const float* __restrict__ al2, const float* __restrict__ ar2)
{
    __shared__ float sW2[128*32], sR2[128*32];
    __shared__ float sP[128], sQ[128], sR[128];
    __shared__ float sal2[32], sar2[32];
    int tid = threadIdx.x;
    for (int i = tid; i < 4096; i += 256) { sW2[i] = W2[i]; sR2[i] = res2[i]; }
    if (tid < 128) {
        float sc = g1g[tid] * rsqrtf(g1v[tid] + 1e-5f);
        sP[tid] = W1[tid]  * sc;
        sQ[tid] = res1[tid]* sc;
        sR[tid] = b1[tid]*sc + g1b[tid] - g1m[tid]*sc;
    }
    if (tid < 32) { sal2[tid] = al2[tid]; sar2[tid] = ar2[tid]; }
    __syncthreads();

    int lane = tid & 31;
    int wid  = blockIdx.x*8 + (tid >> 5);
    int nwarp = gridDim.x*8;

    for (int base = wid*4; base < NN; base += nwarp*4) {
        float h1v[4][4];
        float f2[4] = {0,0,0,0}, r2[4] = {0,0,0,0};
        #pragma unroll
        for (int m = 0; m < 4; m++) {
            int n = base + m;
            float f = feat[n];
            float4 aux = *(const float4*)&d_aux1[n*4];
            float t0 = aux.x > 0.f ? aux.y/aux.x : 0.f;
            float t1 = aux.z > 0.f ? aux.w/aux.z : 0.f;
            #pragma unroll
            for (int q = 0; q < 4; q++) {
                int hd = lane + 32*q;
                float th = (q < 2) ? t0 : t1;
                h1v[m][q] = fmaxf(fmaf(sP[hd], th, fmaf(sQ[hd], f, sR[hd])), 0.f);
            }
        }
        #pragma unroll
        for (int q = 0; q < 4; q++) {
            #pragma unroll 8
            for (int kk = 0; kk < 32; kk++) {
                int k = q*32 + kk;
                float w = sW2[k*32 + lane];
                float r = sR2[k*32 + lane];
                #pragma unroll
                for (int m = 0; m < 4; m++) {
                    float hk = __shfl_sync(0xffffffffu, h1v[m][q], kk);
                    f2[m] = fmaf(hk, w, f2[m]);
                    r2[m] = fmaf(hk, r, r2[m]);
                }
            }
        }
        #pragma unroll
        for (int m = 0; m < 4; m++) {
            int n = base + m;
            d_feat2[n*32 + lane] = f2[m];
            d_res2p[n*32 + lane] = r2[m];
            float vl = f2[m]*sal2[lane], vr = f2[m]*sar2[lane];
            #pragma unroll
            for (int o = 16; o > 0; o >>= 1) {
                vl += __shfl_xor_sync(0xffffffffu, vl, o);
                vr += __shfl_xor_sync(0xffffffffu, vr, o);
            }
            if (lane == 0) { d_el2[n] = vl; d_er2[n] = vr; }
        }
    }
}

// ---------------- layer2 edge pass (single, no max): exp-sum + 32-wide weighted scatter --
__global__ void k_e2(const int* __restrict__ src, const int* __restrict__ dst) {
    long long t = (long long)blockIdx.x*blockDim.x + threadIdx.x;
    int e = (int)(t >> 3);
    int q = (int)(t & 7);
    if (e >= NE) return;
    int s = src[e], d = dst[e];
    float ev = LRELU(d_el2[s] + d_er2[d]);
    float a = __expf(ev);
    if (q == 0) atomicAdd(&d_s2[d], a);
    float4 v = *(const float4*)&d_feat2[s*32 + q*4];
    redAdd4(&d_rst2[d*32 + q*4], a*v.x, a*v.y, a*v.z, a*v.w);
}

// ---------------- node kernel 2: h2 + BN2 + ReLU, store h2, full decoder -> recon ----------
__global__ void __launch_bounds__(256) k_node2(
    const float* __restrict__ b2,
    const float* __restrict__ g2g, const float* __restrict__ g2b,
    const float* __restrict__ g2m, const float* __restrict__ g2v,
    const float* __restrict__ Wd1, const float* __restrict__ bd1,
    const float* __restrict__ gdg, const float* __restrict__ gdb,
    const float* __restrict__ gdm, const float* __restrict__ gdv,
    const float* __restrict__ Wd2, const float* __restrict__ bd2,
    float* __restrict__ out)
{
    __shared__ float sWd1[32*128];
    __shared__ float sSCD[128], sSHD[128], sWd2[128];
    __shared__ float sB2[32], sSC2[32], sSH2[32];
    int tid = threadIdx.x;
    for (int i = tid; i < 4096; i += 256) sWd1[i] = Wd1[i];
    if (tid < 128) {
        float sc = gdg[tid] * rsqrtf(gdv[tid] + 1e-5f);
        sSCD[tid] = sc;
        sSHD[tid] = fmaf(bd1[tid] - gdm[tid], sc, gdb[tid]);
        sWd2[tid] = Wd2[tid];
    }
    if (tid < 32) {
        float sc = g2g[tid] * rsqrtf(g2v[tid] + 1e-5f);
        sSC2[tid] = sc;
        sSH2[tid] = g2b[tid] - g2m[tid]*sc;
        sB2[tid]  = b2[tid];
    }
    __syncthreads();
    float bd2v = bd2[0];

    int lane = tid & 31;
    int wid  = blockIdx.x*8 + (tid >> 5);
    int nwarp = gridDim.x*8;

    for (int n = wid; n < NN; n += nwarp) {
        float s2v = d_s2[n];
        float rv  = d_rst2[n*32 + lane];
        float x = (s2v > 0.f ? rv/s2v : 0.f) + d_res2p[n*32 + lane] + sB2[lane];
        float h2v = fmaxf(fmaf(x, sSC2[lane], sSH2[lane]), 0.f);
        d_h2[n*32 + lane] = h2v;

        float y0 = 0.f, y1 = 0.f, y2 = 0.f, y3 = 0.f;
        #pragma unroll 8
        for (int k = 0; k < 32; k++) {
            float hk = __shfl_sync(0xffffffffu, h2v, k);
            y0 = fmaf(hk, sWd1[k*128 + lane     ], y0);
            y1 = fmaf(hk, sWd1[k*128 + lane + 32], y1);
            y2 = fmaf(hk, sWd1[k*128 + lane + 64], y2);
            y3 = fmaf(hk, sWd1[k*128 + lane + 96], y3);
        }
        float acc;
        acc  = fmaxf(fmaf(y0, sSCD[lane     ], sSHD[lane     ]), 0.f) * sWd2[lane     ];
        acc += fmaxf(fmaf(y1, sSCD[lane + 32], sSHD[lane + 32]), 0.f) * sWd2[lane + 32];
        acc += fmaxf(fmaf(y2, sSCD[lane + 64], sSHD[lane + 64]), 0.f) * sWd2[lane + 64];
        acc += fmaxf(fmaf(y3, sSCD[lane + 96], sSHD[lane + 96]), 0.f) * sWd2[lane + 96];
        #pragma unroll
        for (int o = 16; o > 0; o >>= 1) acc += __shfl_xor_sync(0xffffffffu, acc, o);
        if (lane == 0) out[2048 + n] = acc + bd2v;
    }
}

// ---------------- graph mean-pool (graph_ids sorted; binary-search bounds) ----------------
__global__ void k_pool(const int* __restrict__ gids, float* __restrict__ out) {
    int g = blockIdx.x;
    int a = 0, b = NN;
    while (a < b) { int mid = (a+b) >> 1; if (gids[mid] < g) a = mid+1; else b = mid; }
    int lo = a;
    a = lo; b = NN;
    while (a < b) { int mid = (a+b) >> 1; if (gids[mid] < g+1) a = mid+1; else b = mid; }
    int hi = a;

    __shared__ float sacc[256];
    int tid = threadIdx.x, lane = tid & 31, grp = tid >> 5;
    float acc = 0.f;
    for (int n = lo + grp; n < hi; n += 8) acc += d_h2[n*32 + lane];
    sacc[tid] = acc;
    __syncthreads();
    if (tid < 128) sacc[tid] += sacc[tid + 128];
    __syncthreads();
    if (tid < 64)  sacc[tid] += sacc[tid + 64];
    __syncthreads();
    if (tid < 32) {
        float v = sacc[tid] + sacc[tid + 32];
        float cnt = (float)(hi - lo);
        out[g*32 + tid] = v / fmaxf(cnt, 1.f);
    }
}

// ---------------- launch ----------------
extern "C" void kernel_launch(void* const* d_in, const int* in_sizes, int n_in,
                              void* d_out, int out_size) {
    const float* feat = (const float*)d_in[0];
    const float* W1   = (const float*)d_in[1];
    const float* al1  = (const float*)d_in[2];
    const float* ar1  = (const float*)d_in[3];
    const float* res1 = (const float*)d_in[4];
    const float* b1   = (const float*)d_in[5];
    const float* g1g  = (const float*)d_in[6];
    const float* g1b  = (const float*)d_in[7];
    const float* g1m  = (const float*)d_in[8];
    const float* g1v  = (const float*)d_in[9];
    const float* W2   = (const float*)d_in[10];
    const float* al2  = (const float*)d_in[11];
    const float* ar2  = (const float*)d_in[12];
    const float* res2 = (const float*)d_in[13];
    const float* b2   = (const float*)d_in[14];
    const float* g2g  = (const float*)d_in[15];
    const float* g2b  = (const float*)d_in[16];
    const float* g2m  = (const float*)d_in[17];
    const float* g2v  = (const float*)d_in[18];
    const float* Wd1  = (const float*)d_in[19];
    const float* bd1  = (const float*)d_in[20];
    const float* gdg  = (const float*)d_in[21];
    const float* gdb  = (const float*)d_in[22];
    const float* gdm  = (const float*)d_in[23];
    const float* gdv  = (const float*)d_in[24];
    const float* Wd2  = (const float*)d_in[25];
    const float* bd2  = (const float*)d_in[26];
    const int* src    = (const int*)d_in[27];
    const int* dst    = (const int*)d_in[28];
    const int* gids   = (const int*)d_in[29];
    float* out = (float*)d_out;

    k_init<<<512, 256>>>(W1, al1, ar1);
    k_e1<<<(NE + 255)/256, 256>>>(src, dst, feat);
    k_node1<<<888, 256>>>(feat, W1, res1, b1, g1g, g1b, g1m, g1v, W2, res2, al2, ar2);
    k_e2<<<(NE*8 + 255)/256, 256>>>(src, dst);
    k_node2<<<888, 256>>>(b2, g2g, g2b, g2m, g2v, Wd1, bd1, gdg, gdb, gdm, gdv, Wd2, bd2, out);
    k_pool<<<NG, 256>>>(gids, out);
}

// round 3
// speedup vs baseline: 1.5332x; 1.2416x over previous
#include <cuda_runtime.h>

#define NN 50000
#define NE 800000
#define NG 64
#define LRELU(x) ((x) > 0.f ? (x) : 0.2f*(x))

// ---------------- workspaces (static __device__, no allocation) ----------------
__device__ float d_c1[4];                                   // cl0, cl1, cr0, cr1
__device__ __align__(16) float d_aux1[NN*4];                // {s0, num0, s1, num1}
__device__ __align__(16) float d_feat2[NN*32];
__device__ __align__(16) float d_res2p[NN*32];
__device__ float d_el2[NN];
__device__ float d_er2[NN];
__device__ float d_s2[NN];
__device__ __align__(16) float d_rst2[NN*32];
__device__ __align__(16) float d_h2[NN*32];

// ---------------- helpers ----------------
__device__ __forceinline__ void redAdd4(float* addr, float a, float b, float c, float d) {
    asm volatile("red.global.add.v4.f32 [%0], {%1, %2, %3, %4};"
                 :: "l"(addr), "f"(a), "f"(b), "f"(c), "f"(d) : "memory");
}

// ---------------- init: zero accumulators + compute layer1 attention constants ----------
__global__ void k_init(const float* __restrict__ W1, const float* __restrict__ al1,
                       const float* __restrict__ ar1) {
    int i = blockIdx.x*blockDim.x + threadIdx.x;
    int stride = gridDim.x*blockDim.x;
    float4 z = make_float4(0.f, 0.f, 0.f, 0.f);
    for (int j = i; j < NN;    j += stride) ((float4*)d_aux1)[j] = z;
    for (int j = i; j < NN*8;  j += stride) ((float4*)d_rst2)[j] = z;
    for (int j = i; j < NN;    j += stride) d_s2[j] = 0.f;

    if (blockIdx.x == 0) {
        __shared__ float sl[128], sr[128];
        int t = threadIdx.x;
        if (t < 128) {
            float w = W1[t];
            sl[t] = w * al1[t];
            sr[t] = w * ar1[t];
        }
        __syncthreads();
        for (int off = 32; off > 0; off >>= 1) {
            if (t < 128 && (t & 63) < off) { sl[t] += sl[t+off]; sr[t] += sr[t+off]; }
            __syncthreads();
        }
        if (t < 128 && (t & 63) == 0) { d_c1[t>>6] = sl[t]; d_c1[2 + (t>>6)] = sr[t]; }
    }
}

// ---------------- layer1 edge pass (single, no max): exp-sum + weighted feat sum -------
__global__ void k_e1(const int* __restrict__ src, const int* __restrict__ dst,
                     const float* __restrict__ feat) {
    int e = blockIdx.x*blockDim.x + threadIdx.x;
    if (e >= NE) return;
    int s = src[e], d = dst[e];
    float fs = feat[s], fd = feat[d];
    float e0 = LRELU(d_c1[0]*fs + d_c1[2]*fd);
    float e1 = LRELU(d_c1[1]*fs + d_c1[3]*fd);
    float a0 = __expf(e0);
    float a1 = __expf(e1);
    redAdd4(&d_aux1[d*4], a0, a0*fs, a1, a1*fs);
}

// ---------------- node kernel 1: h1 -> feat2, res2p, el2, er2 (smem-transpose GEMV) ----
__global__ void __launch_bounds__(256) k_node1(
    const float* __restrict__ feat, const float* __restrict__ W1,
    const float* __restrict__ res1, const float* __restrict__ b1,
    const float* __restrict__ g1g, const float* __restrict__ g1b,
    const float* __restrict__ g1m, const float* __restrict__ g1v,
    const float* __restrict__ W2, const float* __restrict__ res2,
    const float* __restrict__ al2, const float* __restrict__ ar2)
{
    __shared__ float2 sWR[4096];        // interleaved {W2[k][j], res2[k][j]}  32KB
    __shared__ float4 sH4[8*128];       // per-warp h1 transpose: [warp][k] -> 4 nodes  16KB
    int tid = threadIdx.x;
    for (int i = tid; i < 4096; i += 256) sWR[i] = make_float2(W2[i], res2[i]);

    int lane = tid & 31;
    int warp = tid >> 5;
    float4* sHw = &sH4[warp*128];

    // per-lane constants (fused BN1 into projection): hd = lane + 32q
    float Pq[4], Qq[4], Rq[4];
    #pragma unroll
    for (int q = 0; q < 4; q++) {
        int hd = lane + 32*q;
        float sc = g1g[hd] * rsqrtf(g1v[hd] + 1e-5f);
        Pq[q] = W1[hd]  * sc;
        Qq[q] = res1[hd]* sc;
        Rq[q] = fmaf(b1[hd] - g1m[hd], sc, g1b[hd]);
    }
    float al2l = al2[lane], ar2l = ar2[lane];
    __syncthreads();

    int wid  = blockIdx.x*8 + warp;
    int nwarp = gridDim.x*8;

    for (int base = wid*4; base < NN; base += nwarp*4) {
        // phase A: compute h1 for 4 nodes, store transposed (warp-private)
        #pragma unroll
        for (int m = 0; m < 4; m++) {
            int n = base + m;
            float f = feat[n];
            float4 aux = *(const float4*)&d_aux1[n*4];
            float t0 = aux.x > 0.f ? __fdividef(aux.y, aux.x) : 0.f;
            float t1 = aux.z > 0.f ? __fdividef(aux.w, aux.z) : 0.f;
            #pragma unroll
            for (int q = 0; q < 4; q++) {
                float th = (q < 2) ? t0 : t1;
                float h = fmaxf(fmaf(Pq[q], th, fmaf(Qq[q], f, Rq[q])), 0.f);
                // store scalar into the m-th component of row k = lane+32q
                ((float*)&sHw[lane + 32*q])[m] = h;
            }
        }
        __syncwarp();

        // phase B: dual GEMV  f2 = h1 @ W2, r2 = h1 @ res2
        float f2[4] = {0,0,0,0}, r2[4] = {0,0,0,0};
        #pragma unroll 8
        for (int k = 0; k < 128; k++) {
            float4 h4 = sHw[k];               // broadcast: h1[k] for nodes m=0..3
            float2 wr = sWR[k*32 + lane];
            f2[0] = fmaf(h4.x, wr.x, f2[0]);  r2[0] = fmaf(h4.x, wr.y, r2[0]);
            f2[1] = fmaf(h4.y, wr.x, f2[1]);  r2[1] = fmaf(h4.y, wr.y, r2[1]);
            f2[2] = fmaf(h4.z, wr.x, f2[2]);  r2[2] = fmaf(h4.z, wr.y, r2[2]);
            f2[3] = fmaf(h4.w, wr.x, f2[3]);  r2[3] = fmaf(h4.w, wr.y, r2[3]);
        }
        __syncwarp();

        #pragma unroll
        for (int m = 0; m < 4; m++) {
            int n = base + m;
            d_feat2[n*32 + lane] = f2[m];
            d_res2p[n*32 + lane] = r2[m];
            float vl = f2[m]*al2l, vr = f2[m]*ar2l;
            #pragma unroll
            for (int o = 16; o > 0; o >>= 1) {
                vl += __shfl_xor_sync(0xffffffffu, vl, o);
                vr += __shfl_xor_sync(0xffffffffu, vr, o);
            }
            if (lane == 0) { d_el2[n] = vl; d_er2[n] = vr; }
        }
    }
}

// ---------------- layer2 edge pass: exp once per edge (shfl-broadcast), 8-lane scatter --
__global__ void k_e2(const int* __restrict__ src, const int* __restrict__ dst) {
    int t = blockIdx.x*blockDim.x + threadIdx.x;
    int e = t >> 3;
    int q = t & 7;
    if (e >= NE) return;
    int lane = threadIdx.x & 31;
    int s = src[e], d = dst[e];
    float a = 0.f;
    if (q == 0) {
        float ev = LRELU(d_el2[s] + d_er2[d]);
        a = __expf(ev);
        atomicAdd(&d_s2[d], a);
    }
    a = __shfl_sync(0xffffffffu, a, lane & 24);
    float4 v = *(const float4*)&d_feat2[s*32 + q*4];
    redAdd4(&d_rst2[d*32 + q*4], a*v.x, a*v.y, a*v.z, a*v.w);
}

// ---------------- node kernel 2: h2 + BN2 + ReLU + full decoder (4 nodes/warp) ---------
__global__ void __launch_bounds__(256) k_node2(
    const float* __restrict__ b2,
    const float* __restrict__ g2g, const float* __restrict__ g2b,
    const float* __restrict__ g2m, const float* __restrict__ g2v,
    const float* __restrict__ Wd1, const float* __restrict__ bd1,
    const float* __restrict__ gdg, const float* __restrict__ gdb,
    const float* __restrict__ gdm, const float* __restrict__ gdv,
    const float* __restrict__ Wd2, const float* __restrict__ bd2,
    float* __restrict__ out)
{
    __shared__ float4 sW4[32*32];   // Wd1 reordered: [k][lane] -> cols {lane,+32,+64,+96}, 16KB
    int tid = threadIdx.x;
    for (int i = tid; i < 1024; i += 256) {
        int k = i >> 5, l = i & 31;
        sW4[i] = make_float4(Wd1[k*128 + l], Wd1[k*128 + l + 32],
                             Wd1[k*128 + l + 64], Wd1[k*128 + l + 96]);
    }
    int lane = tid & 31;
    // per-lane decoder BN constants: columns lane+32j
    float scd[4], shd[4], wd2l[4];
    #pragma unroll
    for (int j = 0; j < 4; j++) {
        int c = lane + 32*j;
        float sc = gdg[c] * rsqrtf(gdv[c] + 1e-5f);
        scd[j] = sc;
        shd[j] = fmaf(bd1[c] - gdm[c], sc, gdb[c]);
        wd2l[j] = Wd2[c];
    }
    float sc2l, sh2l, b2l;
    {
        float sc = g2g[lane] * rsqrtf(g2v[lane] + 1e-5f);
        sc2l = sc;
        sh2l = g2b[lane] - g2m[lane]*sc;
        b2l  = b2[lane];
    }
    float bd2v = bd2[0];
    __syncthreads();

    int wid  = blockIdx.x*8 + (tid >> 5);
    int nwarp = gridDim.x*8;

    for (int base = wid*4; base < NN; base += nwarp*4) {
        float h2v[4];
        #pragma unroll
        for (int m = 0; m < 4; m++) {
            int n = base + m;
            float s2v = d_s2[n];
            float rv  = d_rst2[n*32 + lane];
            float x = (s2v > 0.f ? __fdividef(rv, s2v) : 0.f) + d_res2p[n*32 + lane] + b2l;
            h2v[m] = fmaxf(fmaf(x, sc2l, sh2l), 0.f);
            d_h2[n*32 + lane] = h2v[m];
        }
        float y[4][4] = {{0,0,0,0},{0,0,0,0},{0,0,0,0},{0,0,0,0}};
        #pragma unroll 8
        for (int k = 0; k < 32; k++) {
            float4 w4 = sW4[k*32 + lane];
            #pragma unroll
            for (int m = 0; m < 4; m++) {
                float hk = __shfl_sync(0xffffffffu, h2v[m], k);
                y[m][0] = fmaf(hk, w4.x, y[m][0]);
                y[m][1] = fmaf(hk, w4.y, y[m][1]);
                y[m][2] = fmaf(hk, w4.z, y[m][2]);
                y[m][3] = fmaf(hk, w4.w, y[m][3]);
            }
        }
        #pragma unroll
        for (int m = 0; m < 4; m++) {
            float acc = 0.f;
            #pragma unroll
            for (int j = 0; j < 4; j++)
                acc += fmaxf(fmaf(y[m][j], scd[j], shd[j]), 0.f) * wd2l[j];
            #pragma unroll
            for (int o = 16; o > 0; o >>= 1) acc += __shfl_xor_sync(0xffffffffu, acc, o);
            if (lane == 0) out[2048 + base + m] = acc + bd2v;
        }
    }
}

// ---------------- graph mean-pool (graph_ids sorted; binary-search bounds) ----------------
__global__ void k_pool(const int* __restrict__ gids, float* __restrict__ out) {
    int g = blockIdx.x;
    int a = 0, b = NN;
    while (a < b) { int mid = (a+b) >> 1; if (gids[mid] < g) a = mid+1; else b = mid; }
    int lo = a;
    a = lo; b = NN;
    while (a < b) { int mid = (a+b) >> 1; if (gids[mid] < g+1) a = mid+1; else b = mid; }
    int hi = a;

    __shared__ float sacc[256];
    int tid = threadIdx.x, lane = tid & 31, grp = tid >> 5;
    float acc = 0.f;
    for (int n = lo + grp; n < hi; n += 8) acc += d_h2[n*32 + lane];
    sacc[tid] = acc;
    __syncthreads();
    if (tid < 128) sacc[tid] += sacc[tid + 128];
    __syncthreads();
    if (tid < 64)  sacc[tid] += sacc[tid + 64];
    __syncthreads();
    if (tid < 32) {
        float v = sacc[tid] + sacc[tid + 32];
        float cnt = (float)(hi - lo);
        out[g*32 + tid] = v / fmaxf(cnt, 1.f);
    }
}

// ---------------- launch ----------------
extern "C" void kernel_launch(void* const* d_in, const int* in_sizes, int n_in,
                              void* d_out, int out_size) {
    const float* feat = (const float*)d_in[0];
    const float* W1   = (const float*)d_in[1];
    const float* al1  = (const float*)d_in[2];
    const float* ar1  = (const float*)d_in[3];
    const float* res1 = (const float*)d_in[4];
    const float* b1   = (const float*)d_in[5];
    const float* g1g  = (const float*)d_in[6];
    const float* g1b  = (const float*)d_in[7];
    const float* g1m  = (const float*)d_in[8];
    const float* g1v  = (const float*)d_in[9];
    const float* W2   = (const float*)d_in[10];
    const float* al2  = (const float*)d_in[11];
    const float* ar2  = (const float*)d_in[12];
    const float* res2 = (const float*)d_in[13];
    const float* b2   = (const float*)d_in[14];
    const float* g2g  = (const float*)d_in[15];
    const float* g2b  = (const float*)d_in[16];
    const float* g2m  = (const float*)d_in[17];
    const float* g2v  = (const float*)d_in[18];
    const float* Wd1  = (const float*)d_in[19];
    const float* bd1  = (const float*)d_in[20];
    const float* gdg  = (const float*)d_in[21];
    const float* gdb  = (const float*)d_in[22];
    const float* gdm  = (const float*)d_in[23];
    const float* gdv  = (const float*)d_in[24];
    const float* Wd2  = (const float*)d_in[25];
    const float* bd2  = (const float*)d_in[26];
    const int* src    = (const int*)d_in[27];
    const int* dst    = (const int*)d_in[28];
    const int* gids   = (const int*)d_in[29];
    float* out = (float*)d_out;

    k_init<<<512, 256>>>(W1, al1, ar1);
    k_e1<<<(NE + 255)/256, 256>>>(src, dst, feat);
    k_node1<<<592, 256>>>(feat, W1, res1, b1, g1g, g1b, g1m, g1v, W2, res2, al2, ar2);
    k_e2<<<(NE*8 + 255)/256, 256>>>(src, dst);
    k_node2<<<888, 256>>>(b2, g2g, g2b, g2m, g2v, Wd1, bd1, gdg, gdb, gdm, gdv, Wd2, bd2, out);
    k_pool<<<NG, 256>>>(gids, out);
}